// round 1
// baseline (speedup 1.0000x reference)
#include <cuda_runtime.h>
#include <math.h>

#define SUBN  20
#define ENO   2000
#define INO   500
#define TDATA 10000
#define TSYN  200
#define THIST 50

// ---------------- scratch (device globals; no allocation allowed) ----------
__device__ int   g_asgE[ENO];
__device__ int   g_asgI[INO];
__device__ float g_inE[SUBN * TDATA];          // transposed [s][t]
__device__ float g_inI[SUBN * TDATA];
__device__ float g_kS[SUBN * 2 * TSYN];        // syn kernels (spiking path)
__device__ float g_kN[SUBN * 2 * TSYN];        // syn kernels (non-spiking)
__device__ float g_synS[(TDATA + 1) * SUBN];   // [t][i], 1 padded row (zero-init)
__device__ float g_synN[(TDATA + 1) * SUBN];

// ---------------- phase 1: one-hot -> assignment indices -------------------
__global__ void assign_kernel(const float* __restrict__ Ce,
                              const float* __restrict__ Ci) {
    int j = blockIdx.x * blockDim.x + threadIdx.x;
    if (j < ENO) {
        int s = 0;
        #pragma unroll
        for (int k = 0; k < SUBN; k++) if (Ce[k * ENO + j] > 0.5f) s = k;
        g_asgE[j] = s;
    }
    if (j < INO) {
        int s = 0;
        #pragma unroll
        for (int k = 0; k < SUBN; k++) if (Ci[k * INO + j] > 0.5f) s = k;
        g_asgI[j] = s;
    }
}

// ---------------- phase 2: sparse scatter-reduce S @ C^T -------------------
__global__ void reduce_kernel(const float* __restrict__ Se,
                              const float* __restrict__ Si, int T) {
    int t = blockIdx.x;
    if (t >= T) return;
    __shared__ float acc[2 * SUBN];
    int tid = threadIdx.x;
    if (tid < 2 * SUBN) acc[tid] = 0.0f;
    __syncthreads();
    for (int j = tid; j < ENO; j += blockDim.x) {
        float v = Se[(size_t)t * ENO + j];
        if (v != 0.0f) atomicAdd(&acc[g_asgE[j]], v);
    }
    for (int j = tid; j < INO; j += blockDim.x) {
        float v = Si[(size_t)t * INO + j];
        if (v != 0.0f) atomicAdd(&acc[SUBN + g_asgI[j]], v);
    }
    __syncthreads();
    if (tid < SUBN)            g_inE[tid * TDATA + t] = acc[tid];
    else if (tid < 2 * SUBN)   g_inI[(tid - SUBN) * TDATA + t] = acc[tid];
}

// ---------------- phase 3: build synaptic kernels (double, once) -----------
__global__ void kbuild_kernel(const float* __restrict__ Ws,  const float* __restrict__ Wn,
                              const float* __restrict__ TauS, const float* __restrict__ TauN,
                              const float* __restrict__ Ds,  const float* __restrict__ Dn) {
    int idx = blockIdx.x * blockDim.x + threadIdx.x;
    if (idx >= 2 * SUBN * 2 * TSYN) return;
    int k   = idx % TSYN;
    int c   = (idx / TSYN) % 2;
    int s   = (idx / (TSYN * 2)) % SUBN;
    int set = idx / (TSYN * 2 * SUBN);
    const float* W   = set ? Wn   : Ws;
    const float* Tau = set ? TauN : TauS;
    const float* D   = set ? Dn   : Ds;
    double ts = (double)k - exp((double)D[s * 2 + c]);
    if (ts < 0.0) ts = 0.0;
    double acc = 0.0;
    for (int b = 0; b < 3; b++) {
        double Tb = exp((double)Tau[b * 2 + c]);
        double u  = ts / Tb;
        acc += (double)W[s * 6 + b * 2 + c] * u * exp(-u);
    }
    float* out = set ? g_kN : g_kS;
    out[(s * 2 + c) * TSYN + k] = (float)acc;
}

// ---------------- phase 4: causal FIR (200 taps) ----------------------------
__global__ void conv_kernel(int T) {
    const int i  = blockIdx.y;
    const int t0 = blockIdx.x * 256;
    __shared__ float she[256 + TSYN - 1];
    __shared__ float shi[256 + TSYN - 1];
    __shared__ float kse[TSYN], ksi[TSYN], kne[TSYN], kni[TSYN];
    int tid = threadIdx.x;
    for (int j = tid; j < 256 + TSYN - 1; j += 256) {
        int tg = t0 - (TSYN - 1) + j;
        bool ok = (tg >= 0 && tg < T);
        she[j] = ok ? g_inE[i * TDATA + tg] : 0.0f;
        shi[j] = ok ? g_inI[i * TDATA + tg] : 0.0f;
    }
    for (int k = tid; k < TSYN; k += 256) {
        kse[k] = g_kS[(i * 2 + 0) * TSYN + k];
        ksi[k] = g_kS[(i * 2 + 1) * TSYN + k];
        kne[k] = g_kN[(i * 2 + 0) * TSYN + k];
        kni[k] = g_kN[(i * 2 + 1) * TSYN + k];
    }
    __syncthreads();
    int t = t0 + tid;
    if (t < T) {
        float as = 0.0f, an = 0.0f;
        #pragma unroll 4
        for (int k = 0; k < TSYN; k++) {
            float xe = she[tid + (TSYN - 1) - k];
            float xi = shi[tid + (TSYN - 1) - k];
            as += xe * kse[k] + xi * ksi[k];
            an += xe * kne[k] + xi * kni[k];
        }
        g_synS[t * SUBN + i] = as;
        g_synN[t * SUBN + i] = an;
    }
}

// ---------------- phase 5: single-warp sequential scan ----------------------
// exact truncated-window IIR for the 4 filter families; g(0)=0 means z(t-1)
// enters only via the binary coupling -> 4x5-bit LUT gather; z distributed via
// ballot; everything else shadow-computed one step ahead.
#define FUPD(f, x, xo) {                                        \
    float D_ = E[f] - (xo) * fa49[f];                           \
    F[f] = fa[f] * (F[f] - (xo) * fg49[f]) + faot[f] * D_;      \
    E[f] = (x) + fa[f] * D_; }

__global__ void __launch_bounds__(32, 1)
scan_kernel(const float* __restrict__ Cden,
            const float* __restrict__ WsH, const float* __restrict__ WnH,
            const float* __restrict__ TsH, const float* __restrict__ TnH,
            const float* __restrict__ WsP, const float* __restrict__ WnP,
            const float* __restrict__ TsP, const float* __restrict__ TnP,
            const float* __restrict__ WsSub, const float* __restrict__ WnSub,
            const float* __restrict__ ThS, const float* __restrict__ ThN,
            const float* __restrict__ Vop,
            float* __restrict__ V, float* __restrict__ Z, int T)
{
    const int  lane = threadIdx.x;
    const bool act  = lane < SUBN;
    __shared__ float    lut[4][32][32];
    __shared__ unsigned hist[64];
    __shared__ float    ysh[2][SUBN];

    // row mask of C_den (binary, strictly lower triangular)
    unsigned row = 0;
    if (act) {
        #pragma unroll
        for (int j = 0; j < SUBN; j++)
            if (Cden[lane * SUBN + j] != 0.0f) row |= (1u << j);
    }
    for (int x = lane; x < 64; x += 32) hist[x] = 0u;
    if (act) { ysh[0][lane] = 0.0f; ysh[1][lane] = 0.0f; }

    // 4 x 5-bit LUT of  sum_j C_den[i,j]*W_s_sub[j]*bit_j
    for (int g = 0; g < 4; g++)
        for (int v = 0; v < 32; v++) {
            float s = 0.0f;
            #pragma unroll
            for (int b = 0; b < 5; b++) {
                int j = g * 5 + b;
                if (j < SUBN && ((v >> b) & 1) && ((row >> j) & 1))
                    s += WsSub[j];
            }
            lut[g][v][lane] = s;
        }

    // filter constants: fams 0-2 (z,TsH) 3-5 (c,TsP) 6-8 (z,TnH) 9-11 (c,TnP)
    float fa[12], faot[12], fg49[12], fa49[12];
    {
        const float* taus[4] = { TsH, TsP, TnH, TnP };
        #pragma unroll
        for (int f = 0; f < 4; f++) {
            #pragma unroll
            for (int b = 0; b < 3; b++) {
                double Tb  = exp((double)taus[f][b]);
                double a   = exp(-1.0 / Tb);
                double a49 = pow(a, (double)(THIST - 1));
                fa[f * 3 + b]   = (float)a;
                faot[f * 3 + b] = (float)(a / Tb);
                fa49[f * 3 + b] = (float)a49;
                fg49[f * 3 + b] = (float)((double)(THIST - 1) / Tb * a49);
            }
        }
    }
    bool sameH = (TsH[0] == TnH[0]) && (TsH[1] == TnH[1]) && (TsH[2] == TnH[2]);
    bool sameP = (TsP[0] == TnP[0]) && (TsP[1] == TnP[1]) && (TsP[2] == TnP[2]);

    float F[12], E[12];
    #pragma unroll
    for (int f = 0; f < 12; f++) { F[f] = 0.0f; E[f] = 0.0f; }

    float whs0 = 0, whs1 = 0, whs2 = 0, whn0 = 0, whn1 = 0, whn2 = 0;
    float wps0 = 0, wps1 = 0, wps2 = 0, wpn0 = 0, wpn1 = 0, wpn2 = 0;
    float thS = 0, thN = 0, wns = 0;
    if (act) {
        whs0 = WsH[lane * 3 + 0]; whs1 = WsH[lane * 3 + 1]; whs2 = WsH[lane * 3 + 2];
        whn0 = WnH[lane * 3 + 0]; whn1 = WnH[lane * 3 + 1]; whn2 = WnH[lane * 3 + 2];
        wps0 = WsP[lane * 3 + 0]; wps1 = WsP[lane * 3 + 1]; wps2 = WsP[lane * 3 + 2];
        wpn0 = WnP[lane * 3 + 0]; wpn1 = WnP[lane * 3 + 1]; wpn2 = WnP[lane * 3 + 2];
        thS = ThS[lane]; thN = ThN[lane]; wns = WnSub[lane];
    }
    const float Vo = Vop[0];

    float Ps = act ? (g_synS[lane] - thS) : -1e30f;
    float Pn = act ? (g_synN[lane] - thN) : 0.0f;
    unsigned m_prev = 0;
    __syncwarp();

    for (int t = 0; t < T; t++) {
        // off-chain preloads (padded row exists at t = T-1)
        float syn_ns = act ? g_synS[(t + 1) * SUBN + lane] : -1e30f;
        float syn_nn = act ? g_synN[(t + 1) * SUBN + lane] : 0.0f;

        // ---- critical chain: coupling gather -> spike -> ballot ----
        unsigned mm = m_prev & row;
        float cs = lut[0][mm & 31][lane] + lut[1][(mm >> 5) & 31][lane]
                 + lut[2][(mm >> 10) & 31][lane] + lut[3][(mm >> 15) & 31][lane];
        float ds = Ps + cs;
        bool  z  = (ds >= 0.0f);                  // preserves -0.0 >= 0 semantics
        unsigned m = __ballot_sync(0xFFFFFFFFu, z);

        // ---- ns path (independent chain) ----
        int rb = t & 1;
        float cn = 0.0f;
        unsigned r = row;
        while (r) { int j = __ffs(r) - 1; cn += ysh[rb][j]; r &= r - 1; }
        float dn  = Pn + cn;
        float dcl = fminf(fmaxf(dn, -20.0f), 20.0f);
        float e2  = __expf(-2.0f * dcl);
        float yns = __fdividef(1.0f - e2, 1.0f + e2) * wns;

        // ---- outputs ----
        if (act) Z[t * SUBN + lane] = z ? 1.0f : 0.0f;
        if (lane == 0) V[t] = yns + Vo;

        // ---- shadow: filter state advance + next-step P ----
        hist[t & 63] = m;
        unsigned mold = hist[(t + 14) & 63];      // == m(t-50), zero for t<50
        float zf  = z ? 1.0f : 0.0f;
        float cf  = (float)__popc(m & row);
        float zof = (float)((mold >> lane) & 1u);
        float cof = (float)__popc(mold & row);

        FUPD(0, zf, zof) FUPD(1, zf, zof) FUPD(2, zf, zof)
        FUPD(3, cf, cof) FUPD(4, cf, cof) FUPD(5, cf, cof)
        if (!sameH) { FUPD(6, zf, zof) FUPD(7, zf, zof) FUPD(8, zf, zof) }
        if (!sameP) { FUPD(9, cf, cof) FUPD(10, cf, cof) FUPD(11, cf, cof) }

        float fzn0 = sameH ? F[0] : F[6], fzn1 = sameH ? F[1] : F[7], fzn2 = sameH ? F[2] : F[8];
        float fcn0 = sameP ? F[3] : F[9], fcn1 = sameP ? F[4] : F[10], fcn2 = sameP ? F[5] : F[11];

        Ps = syn_ns - thS + whs0 * F[0] + whs1 * F[1] + whs2 * F[2]
                          + wps0 * F[3] + wps1 * F[4] + wps2 * F[5];
        Pn = syn_nn - thN + whn0 * fzn0 + whn1 * fzn1 + whn2 * fzn2
                          + wpn0 * fcn0 + wpn1 * fcn1 + wpn2 * fcn2;
        if (!act) Ps = -1e30f;

        if (act) ysh[rb ^ 1][lane] = yns;
        __syncwarp();
        m_prev = m;
    }
}

// ---------------- launch ----------------------------------------------------
extern "C" void kernel_launch(void* const* d_in, const int* in_sizes, int n_in,
                              void* d_out, int out_size) {
    const float* Se      = (const float*)d_in[0];
    const float* Si      = (const float*)d_in[1];
    const float* Cden    = (const float*)d_in[2];
    const float* Ce      = (const float*)d_in[3];
    const float* Ci      = (const float*)d_in[4];
    const float* WsSyn   = (const float*)d_in[5];
    const float* WnSyn   = (const float*)d_in[6];
    const float* TauSsyn = (const float*)d_in[7];
    const float* TauNsyn = (const float*)d_in[8];
    const float* DsSyn   = (const float*)d_in[9];
    const float* DnSyn   = (const float*)d_in[10];
    const float* WsH     = (const float*)d_in[11];
    const float* WnH     = (const float*)d_in[12];
    const float* TsH     = (const float*)d_in[13];
    const float* TnH     = (const float*)d_in[14];
    const float* WsP     = (const float*)d_in[15];
    const float* WnP     = (const float*)d_in[16];
    const float* TsP     = (const float*)d_in[17];
    const float* TnP     = (const float*)d_in[18];
    const float* WsSub   = (const float*)d_in[19];
    const float* WnSub   = (const float*)d_in[20];
    const float* ThS     = (const float*)d_in[21];
    const float* ThN     = (const float*)d_in[22];
    const float* Vo      = (const float*)d_in[23];

    int T = in_sizes[0] / ENO;          // 10000
    if (T > TDATA) T = TDATA;
    float* out = (float*)d_out;
    float* V = out;
    float* Z = out + T;

    assign_kernel<<<(ENO + 255) / 256, 256>>>(Ce, Ci);
    reduce_kernel<<<T, 256>>>(Se, Si, T);
    kbuild_kernel<<<(2 * SUBN * 2 * TSYN + 255) / 256, 256>>>(WsSyn, WnSyn, TauSsyn, TauNsyn, DsSyn, DnSyn);
    dim3 cg((T + 255) / 256, SUBN);
    conv_kernel<<<cg, 256>>>(T);
    scan_kernel<<<1, 32>>>(Cden, WsH, WnH, TsH, TnH, WsP, WnP, TsP, TnP,
                           WsSub, WnSub, ThS, ThN, Vo, V, Z, T);
}

// round 2
// speedup vs baseline: 2.0852x; 2.0852x over previous
#include <cuda_runtime.h>
#include <math.h>

#define SUBN  20
#define ENO   2000
#define INO   500
#define TDATA 10000
#define TSYN  200
#define THIST 50
#define CH    128                 // scan staging chunk (power of 2)
#define TPAD  (TDATA + CH)        // padded length, multiple of 4

// ---------------- scratch (device globals; zero-initialized at load) -------
__device__ int   g_asgE[ENO];
__device__ int   g_asgI[INO];
__device__ float g_inE[SUBN * TDATA];           // [s][t]
__device__ float g_inI[SUBN * TDATA];
__device__ float g_kS[SUBN * 2 * TSYN];
__device__ float g_kN[SUBN * 2 * TSYN];
__device__ float g_synST[SUBN * TPAD];          // subunit-major, pad stays 0
__device__ float g_synNT[SUBN * TPAD];

// ---------------- phase 1: one-hot -> assignment indices -------------------
__global__ void assign_kernel(const float* __restrict__ Ce,
                              const float* __restrict__ Ci) {
    int j = blockIdx.x * blockDim.x + threadIdx.x;
    if (j < ENO) {
        int s = 0;
        #pragma unroll
        for (int k = 0; k < SUBN; k++) if (Ce[k * ENO + j] > 0.5f) s = k;
        g_asgE[j] = s;
    }
    if (j < INO) {
        int s = 0;
        #pragma unroll
        for (int k = 0; k < SUBN; k++) if (Ci[k * INO + j] > 0.5f) s = k;
        g_asgI[j] = s;
    }
}

// ---------------- phase 2: sparse scatter-reduce S @ C^T -------------------
__global__ void reduce_kernel(const float* __restrict__ Se,
                              const float* __restrict__ Si, int T) {
    int t = blockIdx.x;
    if (t >= T) return;
    __shared__ float acc[2 * SUBN];
    int tid = threadIdx.x;
    if (tid < 2 * SUBN) acc[tid] = 0.0f;
    __syncthreads();
    for (int j = tid; j < ENO; j += blockDim.x) {
        float v = Se[(size_t)t * ENO + j];
        if (v != 0.0f) atomicAdd(&acc[g_asgE[j]], v);
    }
    for (int j = tid; j < INO; j += blockDim.x) {
        float v = Si[(size_t)t * INO + j];
        if (v != 0.0f) atomicAdd(&acc[SUBN + g_asgI[j]], v);
    }
    __syncthreads();
    if (tid < SUBN)            g_inE[tid * TDATA + t] = acc[tid];
    else if (tid < 2 * SUBN)   g_inI[(tid - SUBN) * TDATA + t] = acc[tid];
}

// ---------------- phase 3: build synaptic kernels ---------------------------
__global__ void kbuild_kernel(const float* __restrict__ Ws,  const float* __restrict__ Wn,
                              const float* __restrict__ TauS, const float* __restrict__ TauN,
                              const float* __restrict__ Ds,  const float* __restrict__ Dn) {
    int idx = blockIdx.x * blockDim.x + threadIdx.x;
    if (idx >= 2 * SUBN * 2 * TSYN) return;
    int k   = idx % TSYN;
    int c   = (idx / TSYN) % 2;
    int s   = (idx / (TSYN * 2)) % SUBN;
    int set = idx / (TSYN * 2 * SUBN);
    const float* W   = set ? Wn   : Ws;
    const float* Tau = set ? TauN : TauS;
    const float* D   = set ? Dn   : Ds;
    double ts = (double)k - exp((double)D[s * 2 + c]);
    if (ts < 0.0) ts = 0.0;
    double acc = 0.0;
    for (int b = 0; b < 3; b++) {
        double Tb = exp((double)Tau[b * 2 + c]);
        double u  = ts / Tb;
        acc += (double)W[s * 6 + b * 2 + c] * u * exp(-u);
    }
    float* out = set ? g_kN : g_kS;
    out[(s * 2 + c) * TSYN + k] = (float)acc;
}

// ---------------- phase 4: causal FIR (200 taps), subunit-major output ------
__global__ void conv_kernel(int T) {
    const int i  = blockIdx.y;
    const int t0 = blockIdx.x * 256;
    __shared__ float she[256 + TSYN - 1];
    __shared__ float shi[256 + TSYN - 1];
    __shared__ float kse[TSYN], ksi[TSYN], kne[TSYN], kni[TSYN];
    int tid = threadIdx.x;
    for (int j = tid; j < 256 + TSYN - 1; j += 256) {
        int tg = t0 - (TSYN - 1) + j;
        bool ok = (tg >= 0 && tg < T);
        she[j] = ok ? g_inE[i * TDATA + tg] : 0.0f;
        shi[j] = ok ? g_inI[i * TDATA + tg] : 0.0f;
    }
    for (int k = tid; k < TSYN; k += 256) {
        kse[k] = g_kS[(i * 2 + 0) * TSYN + k];
        ksi[k] = g_kS[(i * 2 + 1) * TSYN + k];
        kne[k] = g_kN[(i * 2 + 0) * TSYN + k];
        kni[k] = g_kN[(i * 2 + 1) * TSYN + k];
    }
    __syncthreads();
    int t = t0 + tid;
    if (t < T) {
        float as = 0.0f, an = 0.0f;
        #pragma unroll 4
        for (int k = 0; k < TSYN; k++) {
            float xe = she[tid + (TSYN - 1) - k];
            float xi = shi[tid + (TSYN - 1) - k];
            as += xe * kse[k] + xi * ksi[k];
            an += xe * kne[k] + xi * kni[k];
        }
        g_synST[i * TPAD + t] = as;
        g_synNT[i * TPAD + t] = an;
    }
}

// ---------------- phase 5: single-warp sequential scan ----------------------
#define FUPD(f, x, xo) {                                        \
    float D_ = fmaf(-(xo), fa49[f], E[f]);                      \
    F[f] = fmaf(fa[f], fmaf(-(xo), fg49[f], F[f]), faot[f] * D_); \
    E[f] = fmaf(fa[f], D_, (x)); }

#define STAGE(t0) do {                                                         \
    if (act) {                                                                 \
        const float4* __restrict__ pS = (const float4*)(g_synST + lane * TPAD + (t0)); \
        const float4* __restrict__ pN = (const float4*)(g_synNT + lane * TPAD + (t0)); \
        _Pragma("unroll 8")                                                    \
        for (int q = 0; q < CH / 4; q++) {                                     \
            float4 a = pS[q]; float4 b = pN[q];                                \
            shS[4*q+0][lane] = a.x; shS[4*q+1][lane] = a.y;                    \
            shS[4*q+2][lane] = a.z; shS[4*q+3][lane] = a.w;                    \
            shN[4*q+0][lane] = b.x; shN[4*q+1][lane] = b.y;                    \
            shN[4*q+2][lane] = b.z; shN[4*q+3][lane] = b.w;                    \
        }                                                                      \
    }                                                                          \
} while (0)

__global__ void __launch_bounds__(32, 1)
scan_kernel(const float* __restrict__ Cden,
            const float* __restrict__ WsH, const float* __restrict__ WnH,
            const float* __restrict__ TsH, const float* __restrict__ TnH,
            const float* __restrict__ WsP, const float* __restrict__ WnP,
            const float* __restrict__ TsP, const float* __restrict__ TnP,
            const float* __restrict__ WsSub, const float* __restrict__ WnSub,
            const float* __restrict__ ThS, const float* __restrict__ ThN,
            const float* __restrict__ Vop,
            float* __restrict__ V, float* __restrict__ Z, int T)
{
    const int  lane = threadIdx.x;
    const bool act  = lane < SUBN;
    __shared__ float lut[4][32][32];
    __shared__ float shS[CH][21];
    __shared__ float shN[CH][21];

    // binary row mask of C_den (strictly lower triangular)
    unsigned row = 0;
    if (act) {
        #pragma unroll
        for (int j = 0; j < SUBN; j++)
            if (Cden[lane * SUBN + j] != 0.0f) row |= (1u << j);
    }

    // 4 x 5-bit LUT of the spiking coupling  sum_j C[i,j]*W_s_sub[j]*bit_j
    for (int g = 0; g < 4; g++)
        for (int v = 0; v < 32; v++) {
            float s = 0.0f;
            #pragma unroll
            for (int b = 0; b < 5; b++) {
                int j = g * 5 + b;
                if (j < SUBN && ((v >> b) & 1) && ((row >> j) & 1))
                    s += WsSub[j];
            }
            lut[g][v][lane] = s;
        }

    // per-lane register weights for the ns coupling (raw-tanh exchange)
    float rowfW[SUBN];
    #pragma unroll
    for (int k = 0; k < SUBN; k++)
        rowfW[k] = ((row >> k) & 1u) ? WnSub[k] : 0.0f;

    // filter constants: fams 0-2 (z,TsH) 3-5 (c,TsP) 6-8 (z,TnH) 9-11 (c,TnP)
    float fa[12], faot[12], fg49[12], fa49[12];
    {
        const float* taus[4] = { TsH, TsP, TnH, TnP };
        #pragma unroll
        for (int f = 0; f < 4; f++)
            #pragma unroll
            for (int b = 0; b < 3; b++) {
                double Tb  = exp((double)taus[f][b]);
                double a   = exp(-1.0 / Tb);
                double a49 = pow(a, (double)(THIST - 1));
                fa[f * 3 + b]   = (float)a;
                faot[f * 3 + b] = (float)(a / Tb);
                fa49[f * 3 + b] = (float)a49;
                fg49[f * 3 + b] = (float)((double)(THIST - 1) / Tb * a49);
            }
    }
    bool sameH = (TsH[0] == TnH[0]) && (TsH[1] == TnH[1]) && (TsH[2] == TnH[2]);
    bool sameP = (TsP[0] == TnP[0]) && (TsP[1] == TnP[1]) && (TsP[2] == TnP[2]);

    float F[12], E[12];
    #pragma unroll
    for (int f = 0; f < 12; f++) { F[f] = 0.0f; E[f] = 0.0f; }

    float whs0 = 0, whs1 = 0, whs2 = 0, whn0 = 0, whn1 = 0, whn2 = 0;
    float wps0 = 0, wps1 = 0, wps2 = 0, wpn0 = 0, wpn1 = 0, wpn2 = 0;
    float thS = 0, thN = 0, wns = 0;
    if (act) {
        whs0 = WsH[lane * 3 + 0]; whs1 = WsH[lane * 3 + 1]; whs2 = WsH[lane * 3 + 2];
        whn0 = WnH[lane * 3 + 0]; whn1 = WnH[lane * 3 + 1]; whn2 = WnH[lane * 3 + 2];
        wps0 = WsP[lane * 3 + 0]; wps1 = WsP[lane * 3 + 1]; wps2 = WsP[lane * 3 + 2];
        wpn0 = WnP[lane * 3 + 0]; wpn1 = WnP[lane * 3 + 1]; wpn2 = WnP[lane * 3 + 2];
        thS = ThS[lane]; thN = ThN[lane]; wns = WnSub[lane];
    }
    const float Vo = Vop[0];

    STAGE(0);
    __syncwarp();

    float Ps = act ? (shS[0][lane] - thS) : -1e30f;
    float Pn = act ? (shN[0][lane] - thN) : 0.0f;
    unsigned m_prev = 0, m_a = 0, m_b = 0;
    float traw_prev = 0.0f;

    for (int t = 0; t < T; t++) {
        int idx = t + 1;
        if ((idx & (CH - 1)) == 0) {       // uniform branch
            __syncwarp();
            STAGE(idx);
            __syncwarp();
        }

        // ---- z critical chain: coupling LUT -> spike -> ballot ----
        unsigned mm = m_prev & row;
        float cs = (lut[0][mm & 31][lane] + lut[1][(mm >> 5) & 31][lane])
                 + (lut[2][(mm >> 10) & 31][lane] + lut[3][(mm >> 15) & 31][lane]);
        float ds = Ps + cs;
        bool  z  = (ds >= 0.0f);
        unsigned m = __ballot_sync(0xFFFFFFFFu, z);

        // ---- ns chain: shfl exchange of raw tanh + FMA tree ----
        float a0 = 0, a1 = 0, a2 = 0, a3 = 0;
        #pragma unroll
        for (int k = 0; k < SUBN; k += 4) {
            a0 = fmaf(rowfW[k + 0], __shfl_sync(0xFFFFFFFFu, traw_prev, k + 0), a0);
            a1 = fmaf(rowfW[k + 1], __shfl_sync(0xFFFFFFFFu, traw_prev, k + 1), a1);
            a2 = fmaf(rowfW[k + 2], __shfl_sync(0xFFFFFFFFu, traw_prev, k + 2), a2);
            a3 = fmaf(rowfW[k + 3], __shfl_sync(0xFFFFFFFFu, traw_prev, k + 3), a3);
        }
        float dn   = Pn + ((a0 + a1) + (a2 + a3));
        float e2   = __expf(2.0f * dn);                    // tanh = 1 - 2/(e^{2x}+1)
        float traw = 1.0f - __fdividef(2.0f, e2 + 1.0f);   // saturates correctly

        // ---- outputs ----
        if (act) Z[t * SUBN + lane] = z ? 1.0f : 0.0f;
        if (lane == 0) V[t] = traw * wns + Vo;

        // ---- m(t-50) via lane-slot registers (no shared, no syncwarp) ----
        unsigned mold = __shfl_sync(0xFFFFFFFFu, m_b, (t + 14) & 31);
        if (lane == (t & 31)) { m_b = m_a; m_a = m; }

        // ---- shadow: filter advance + next-step drives ----
        float zf  = z ? 1.0f : 0.0f;
        float cf  = (float)__popc(m & row);
        float zof = (float)((mold >> lane) & 1u);
        float cof = (float)__popc(mold & row);

        FUPD(0, zf, zof) FUPD(1, zf, zof) FUPD(2, zf, zof)
        FUPD(3, cf, cof) FUPD(4, cf, cof) FUPD(5, cf, cof)
        if (!sameH) { FUPD(6, zf, zof) FUPD(7, zf, zof) FUPD(8, zf, zof) }
        if (!sameP) { FUPD(9, cf, cof) FUPD(10, cf, cof) FUPD(11, cf, cof) }

        float fzn0 = sameH ? F[0] : F[6], fzn1 = sameH ? F[1] : F[7], fzn2 = sameH ? F[2] : F[8];
        float fcn0 = sameP ? F[3] : F[9], fcn1 = sameP ? F[4] : F[10], fcn2 = sameP ? F[5] : F[11];

        int r = idx & (CH - 1);
        float syn_ns = 0.0f, syn_nn = 0.0f;
        if (act) { syn_ns = shS[r][lane]; syn_nn = shN[r][lane]; }

        Ps = syn_ns - thS + whs0 * F[0] + whs1 * F[1] + whs2 * F[2]
                          + wps0 * F[3] + wps1 * F[4] + wps2 * F[5];
        Pn = syn_nn - thN + whn0 * fzn0 + whn1 * fzn1 + whn2 * fzn2
                          + wpn0 * fcn0 + wpn1 * fcn1 + wpn2 * fcn2;
        if (!act) Ps = -1e30f;

        traw_prev = traw;
        m_prev = m;
    }
}

// ---------------- launch ----------------------------------------------------
extern "C" void kernel_launch(void* const* d_in, const int* in_sizes, int n_in,
                              void* d_out, int out_size) {
    const float* Se      = (const float*)d_in[0];
    const float* Si      = (const float*)d_in[1];
    const float* Cden    = (const float*)d_in[2];
    const float* Ce      = (const float*)d_in[3];
    const float* Ci      = (const float*)d_in[4];
    const float* WsSyn   = (const float*)d_in[5];
    const float* WnSyn   = (const float*)d_in[6];
    const float* TauSsyn = (const float*)d_in[7];
    const float* TauNsyn = (const float*)d_in[8];
    const float* DsSyn   = (const float*)d_in[9];
    const float* DnSyn   = (const float*)d_in[10];
    const float* WsH     = (const float*)d_in[11];
    const float* WnH     = (const float*)d_in[12];
    const float* TsH     = (const float*)d_in[13];
    const float* TnH     = (const float*)d_in[14];
    const float* WsP     = (const float*)d_in[15];
    const float* WnP     = (const float*)d_in[16];
    const float* TsP     = (const float*)d_in[17];
    const float* TnP     = (const float*)d_in[18];
    const float* WsSub   = (const float*)d_in[19];
    const float* WnSub   = (const float*)d_in[20];
    const float* ThS     = (const float*)d_in[21];
    const float* ThN     = (const float*)d_in[22];
    const float* Vo      = (const float*)d_in[23];

    int T = in_sizes[0] / ENO;          // 10000
    if (T > TDATA) T = TDATA;
    float* out = (float*)d_out;
    float* V = out;
    float* Z = out + T;

    assign_kernel<<<(ENO + 255) / 256, 256>>>(Ce, Ci);
    reduce_kernel<<<T, 256>>>(Se, Si, T);
    kbuild_kernel<<<(2 * SUBN * 2 * TSYN + 255) / 256, 256>>>(WsSyn, WnSyn, TauSsyn, TauNsyn, DsSyn, DnSyn);
    dim3 cg((T + 255) / 256, SUBN);
    conv_kernel<<<cg, 256>>>(T);
    scan_kernel<<<1, 32>>>(Cden, WsH, WnH, TsH, TnH, WsP, WnP, TsP, TnP,
                           WsSub, WnSub, ThS, ThN, Vo, V, Z, T);
}

// round 3
// speedup vs baseline: 2.3682x; 1.1357x over previous
#include <cuda_runtime.h>
#include <math.h>

#define SUBN  20
#define ENO   2000
#define INO   500
#define TDATA 10000
#define TSYN  200
#define THIST 50
#define CH    64                   // staging chunk (== sync cadence)
#define RING  1024
#define TPAD  (TDATA + CH)

// ---------------- scratch (device globals; zero-initialized) ---------------
__device__ int   g_asgE[ENO];
__device__ int   g_asgI[INO];
__device__ float g_inE[SUBN * TDATA];
__device__ float g_inI[SUBN * TDATA];
__device__ float g_kS[SUBN * 2 * TSYN];
__device__ float g_kN[SUBN * 2 * TSYN];
__device__ float g_synST[SUBN * TPAD];          // syn_s - Theta_s, [s][t]
__device__ float g_synNT[SUBN * TPAD];          // syn_ns - Theta_ns

// ---------------- phase 1: one-hot -> assignment indices -------------------
__global__ void assign_kernel(const float* __restrict__ Ce,
                              const float* __restrict__ Ci) {
    int j = blockIdx.x * blockDim.x + threadIdx.x;
    if (j < ENO) {
        int s = 0;
        #pragma unroll
        for (int k = 0; k < SUBN; k++) if (Ce[k * ENO + j] > 0.5f) s = k;
        g_asgE[j] = s;
    }
    if (j < INO) {
        int s = 0;
        #pragma unroll
        for (int k = 0; k < SUBN; k++) if (Ci[k * INO + j] > 0.5f) s = k;
        g_asgI[j] = s;
    }
}

// ---------------- phase 2: sparse scatter-reduce S @ C^T -------------------
__global__ void reduce_kernel(const float* __restrict__ Se,
                              const float* __restrict__ Si, int T) {
    int t = blockIdx.x;
    if (t >= T) return;
    __shared__ float acc[2 * SUBN];
    int tid = threadIdx.x;
    if (tid < 2 * SUBN) acc[tid] = 0.0f;
    __syncthreads();
    for (int j = tid; j < ENO; j += blockDim.x) {
        float v = Se[(size_t)t * ENO + j];
        if (v != 0.0f) atomicAdd(&acc[g_asgE[j]], v);
    }
    for (int j = tid; j < INO; j += blockDim.x) {
        float v = Si[(size_t)t * INO + j];
        if (v != 0.0f) atomicAdd(&acc[SUBN + g_asgI[j]], v);
    }
    __syncthreads();
    if (tid < SUBN)            g_inE[tid * TDATA + t] = acc[tid];
    else if (tid < 2 * SUBN)   g_inI[(tid - SUBN) * TDATA + t] = acc[tid];
}

// ---------------- phase 3: build synaptic kernels ---------------------------
__global__ void kbuild_kernel(const float* __restrict__ Ws,  const float* __restrict__ Wn,
                              const float* __restrict__ TauS, const float* __restrict__ TauN,
                              const float* __restrict__ Ds,  const float* __restrict__ Dn) {
    int idx = blockIdx.x * blockDim.x + threadIdx.x;
    if (idx >= 2 * SUBN * 2 * TSYN) return;
    int k   = idx % TSYN;
    int c   = (idx / TSYN) % 2;
    int s   = (idx / (TSYN * 2)) % SUBN;
    int set = idx / (TSYN * 2 * SUBN);
    const float* W   = set ? Wn   : Ws;
    const float* Tau = set ? TauN : TauS;
    const float* D   = set ? Dn   : Ds;
    double ts = (double)k - exp((double)D[s * 2 + c]);
    if (ts < 0.0) ts = 0.0;
    double acc = 0.0;
    for (int b = 0; b < 3; b++) {
        double Tb = exp((double)Tau[b * 2 + c]);
        double u  = ts / Tb;
        acc += (double)W[s * 6 + b * 2 + c] * u * exp(-u);
    }
    float* out = set ? g_kN : g_kS;
    out[(s * 2 + c) * TSYN + k] = (float)acc;
}

// ---------------- phase 4: causal FIR; folds -Theta into the output --------
__global__ void conv_kernel(const float* __restrict__ ThS,
                            const float* __restrict__ ThN, int T) {
    const int i  = blockIdx.y;
    const int t0 = blockIdx.x * 256;
    __shared__ float she[256 + TSYN - 1];
    __shared__ float shi[256 + TSYN - 1];
    __shared__ float kse[TSYN], ksi[TSYN], kne[TSYN], kni[TSYN];
    int tid = threadIdx.x;
    for (int j = tid; j < 256 + TSYN - 1; j += 256) {
        int tg = t0 - (TSYN - 1) + j;
        bool ok = (tg >= 0 && tg < T);
        she[j] = ok ? g_inE[i * TDATA + tg] : 0.0f;
        shi[j] = ok ? g_inI[i * TDATA + tg] : 0.0f;
    }
    for (int k = tid; k < TSYN; k += 256) {
        kse[k] = g_kS[(i * 2 + 0) * TSYN + k];
        ksi[k] = g_kS[(i * 2 + 1) * TSYN + k];
        kne[k] = g_kN[(i * 2 + 0) * TSYN + k];
        kni[k] = g_kN[(i * 2 + 1) * TSYN + k];
    }
    __syncthreads();
    int t = t0 + tid;
    if (t < T) {
        float as = 0.0f, an = 0.0f;
        #pragma unroll 4
        for (int k = 0; k < TSYN; k++) {
            float xe = she[tid + (TSYN - 1) - k];
            float xi = shi[tid + (TSYN - 1) - k];
            as += xe * kse[k] + xi * ksi[k];
            an += xe * kne[k] + xi * kni[k];
        }
        g_synST[i * TPAD + t] = as - ThS[i];
        g_synNT[i * TPAD + t] = an - ThN[i];
    }
}

// ---------------- phase 5: warp-specialized sequential scan -----------------
__device__ __forceinline__ float u2f_small(unsigned x) {  // exact for x < 2^23
    return __uint_as_float(0x4B000000u | x) - 8388608.0f;
}

#define FUPD(f, x, xo) {                                            \
    float D_ = fmaf(-(xo), fa49[f], E[f]);                          \
    F[f] = fmaf(fa[f], fmaf(-(xo), fg49[f], F[f]), faot[f] * D_);   \
    E[f] = fmaf(fa[f], D_, (x)); }

#define MKCONST(tauH, tauP) {                                       \
    const float* taus_[2] = { tauH, tauP };                         \
    for (int ff = 0; ff < 2; ff++)                                  \
        for (int b = 0; b < 3; b++) {                               \
            double Tb  = exp((double)taus_[ff][b]);                 \
            double a   = exp(-1.0 / Tb);                            \
            double a49 = pow(a, (double)(THIST - 1));               \
            fa[ff*3+b]   = (float)a;                                \
            faot[ff*3+b] = (float)(a / Tb);                         \
            fa49[ff*3+b] = (float)a49;                              \
            fg49[ff*3+b] = (float)((double)(THIST - 1) / Tb * a49); \
        } }

#define STAGE(dst, src, t0) {                                               \
    const float4* __restrict__ p_ = (const float4*)((src) + lane * TPAD + (t0)); \
    _Pragma("unroll")                                                       \
    for (int q = 0; q < CH / 4; q++) {                                      \
        float4 a_ = p_[q];                                                  \
        dst[4*q+0][lane] = a_.x; dst[4*q+1][lane] = a_.y;                   \
        dst[4*q+2][lane] = a_.z; dst[4*q+3][lane] = a_.w;                   \
    } }

__global__ void __launch_bounds__(64, 1)
scan_kernel(const float* __restrict__ Cden,
            const float* __restrict__ WsH, const float* __restrict__ WnH,
            const float* __restrict__ TsH, const float* __restrict__ TnH,
            const float* __restrict__ WsP, const float* __restrict__ WnP,
            const float* __restrict__ TsP, const float* __restrict__ TnP,
            const float* __restrict__ WsSub, const float* __restrict__ WnSub,
            const float* __restrict__ Vop,
            float* __restrict__ V, float* __restrict__ Z, int T)
{
    const int tid  = threadIdx.x;
    const int lane = tid & 31;
    const int wrp  = tid >> 5;
    const bool act = lane < SUBN;

    __shared__ float lut[4][32][32];
    __shared__ float shS[CH][32];
    __shared__ float shN[CH][32];
    __shared__ volatile unsigned rm[RING];
    __shared__ volatile int s_prod, s_cons;

    // shared init (both warps)
    for (int x = tid; x < RING; x += 64) rm[x] = 0u;
    for (int x = tid; x < CH * 32; x += 64) {
        ((float*)shS)[x] = 0.0f;
        ((float*)shN)[x] = 0.0f;
    }
    if (tid == 0) { s_prod = 0; s_cons = 0; }

    // per-lane row mask of C_den
    unsigned row = 0;
    if (act) {
        #pragma unroll
        for (int j = 0; j < SUBN; j++)
            if (Cden[lane * SUBN + j] != 0.0f) row |= (1u << j);
    }

    if (wrp == 0) {
        // build 4 x 5-bit spiking-coupling LUT (each lane fills its own column)
        for (int g = 0; g < 4; g++)
            for (int v = 0; v < 32; v++) {
                float s = 0.0f;
                #pragma unroll
                for (int b = 0; b < 5; b++) {
                    int j = g * 5 + b;
                    if (j < SUBN && ((v >> b) & 1) && ((row >> j) & 1))
                        s += WsSub[j];
                }
                lut[g][v][lane] = s;
            }
    }
    __syncthreads();

    if (wrp == 0) {
        // ======================= z warp (producer) ==========================
        float fa[6], faot[6], fa49[6], fg49[6];
        MKCONST(TsH, TsP);
        float F[6], E[6];
        #pragma unroll
        for (int f = 0; f < 6; f++) { F[f] = 0.0f; E[f] = 0.0f; }
        float w0_ = 0, w1_ = 0, w2_ = 0, w3_ = 0, w4_ = 0, w5_ = 0;
        if (act) {
            w0_ = WsH[lane * 3 + 0]; w1_ = WsH[lane * 3 + 1]; w2_ = WsH[lane * 3 + 2];
            w3_ = WsP[lane * 3 + 0]; w4_ = WsP[lane * 3 + 1]; w5_ = WsP[lane * 3 + 2];
        }
        if (act) STAGE(shS, g_synST, 0);
        __syncwarp();

        float Ps = shS[0][lane];
        unsigned m_prev = 0, m_a = 0, m_b = 0;
        float* Zp = Z;

        for (int t = 0; t < T; t++) {
            if ((t & (CH - 1)) == 0 && t) {                 // publish + ring gate
                __threadfence_block();
                if (lane == 0) s_prod = t;
                while (t + CH - s_cons > RING) {}
            }
            if (((t + 1) & (CH - 1)) == 0) {                // stage next chunk
                if (act) STAGE(shS, g_synST, t + 1);
                __syncwarp();
            }

            // critical chain: LUT coupling -> spike -> ballot
            unsigned mm = m_prev & row;
            float cs = (lut[0][mm & 31][lane] + lut[1][(mm >> 5) & 31][lane])
                     + (lut[2][(mm >> 10) & 31][lane] + lut[3][(mm >> 15) & 31][lane]);
            float ds = cs + Ps;
            bool  z  = (ds >= 0.0f);
            unsigned m = __ballot_sync(0xFFFFFFFFu, z);
            if (lane == 0) rm[t & (RING - 1)] = m;

            float zf = z ? 1.0f : 0.0f;
            if (act) Zp[lane] = zf;
            Zp += SUBN;

            // m(t-50) via lane-slot registers
            unsigned mold = __shfl_sync(0xFFFFFFFFu, m_b, (t + 14) & 31);
            if (lane == (t & 31)) { m_b = m_a; m_a = m; }

            float cf  = u2f_small(__popc(m & row));
            float zof = u2f_small((mold >> lane) & 1u);
            float cof = u2f_small(__popc(mold & row));

            FUPD(0, zf, zof) FUPD(1, zf, zof) FUPD(2, zf, zof)
            FUPD(3, cf, cof) FUPD(4, cf, cof) FUPD(5, cf, cof)

            int r = (t + 1) & (CH - 1);
            float syn = shS[r][lane];
            float p0 = fmaf(w0_, F[0], syn);
            float p1 = fmaf(w1_, F[1], w2_ * F[2]);
            float p2 = fmaf(w3_, F[3], w4_ * F[4]);
            float p3 = w5_ * F[5];
            Ps = (p0 + p1) + (p2 + p3);
            if (!act) Ps = 0.0f;
            m_prev = m;
        }
        __threadfence_block();
        if (lane == 0) s_prod = T;
    } else {
        // ======================= ns warp (consumer) =========================
        float fa[6], faot[6], fa49[6], fg49[6];
        MKCONST(TnH, TnP);
        float F[6], E[6];
        #pragma unroll
        for (int f = 0; f < 6; f++) { F[f] = 0.0f; E[f] = 0.0f; }
        float w0_ = 0, w1_ = 0, w2_ = 0, w3_ = 0, w4_ = 0, w5_ = 0, wns = 0;
        if (act) {
            w0_ = WnH[lane * 3 + 0]; w1_ = WnH[lane * 3 + 1]; w2_ = WnH[lane * 3 + 2];
            w3_ = WnP[lane * 3 + 0]; w4_ = WnP[lane * 3 + 1]; w5_ = WnP[lane * 3 + 2];
            wns = WnSub[lane];
        }
        const float Vo = Vop[0];

        // packed sparse gather indices: 4 per word, 8 bits each, pad = 31
        unsigned pw0 = 0x1F1F1F1Fu, pw1 = 0x1F1F1F1Fu, pw2 = 0x1F1F1F1Fu,
                 pw3 = 0x1F1F1F1Fu, pw4 = 0x1F1F1F1Fu;
        {
            unsigned rem = row; int k = 0;
            while (rem) {
                int j = __ffs(rem) - 1; rem &= rem - 1;
                unsigned sh = 8u * (k & 3);
                unsigned cl = ~(0xFFu << sh);
                unsigned in = ((unsigned)j) << sh;
                switch (k >> 2) {
                    case 0: pw0 = (pw0 & cl) | in; break;
                    case 1: pw1 = (pw1 & cl) | in; break;
                    case 2: pw2 = (pw2 & cl) | in; break;
                    case 3: pw3 = (pw3 & cl) | in; break;
                    default: pw4 = (pw4 & cl) | in; break;
                }
                k++;
            }
        }
        int kmax  = (int)__reduce_max_sync(0xFFFFFFFFu, (unsigned)__popc(row));
        int words = (kmax + 3) >> 2;

        if (act) STAGE(shN, g_synNT, 0);
        __syncwarp();

        float Pn  = shN[0][lane];
        float vex = 0.0f;                 // tanh * W_ns_sub (exchanged value)
        float* Vp = V;

        for (int t = 0; t < T; t++) {
            if ((t & (CH - 1)) == 0) {                      // wait for producer
                int need = t + CH; if (need > T) need = T;
                while (s_prod < need) {}
                __threadfence_block();
                if (lane == 0) s_cons = t;
            }
            if (((t + 1) & (CH - 1)) == 0) {
                if (act) STAGE(shN, g_synNT, t + 1);
                __syncwarp();
            }

            unsigned m    = rm[t & (RING - 1)];
            unsigned mold = rm[(t - 50) & (RING - 1)];      // zeros for t < 50

            // ns coupling: sparse shuffle gather of tanh*W_ns_sub
            float c0 = 0, c1 = 0, c2 = 0, c3 = 0;
            if (words > 0) {
                c0 = __shfl_sync(0xFFFFFFFFu, vex, pw0 & 31);
                c1 = __shfl_sync(0xFFFFFFFFu, vex, (pw0 >> 8) & 31);
                c2 = __shfl_sync(0xFFFFFFFFu, vex, (pw0 >> 16) & 31);
                c3 = __shfl_sync(0xFFFFFFFFu, vex, pw0 >> 24);
            }
            if (words > 1) {
                c0 += __shfl_sync(0xFFFFFFFFu, vex, pw1 & 31);
                c1 += __shfl_sync(0xFFFFFFFFu, vex, (pw1 >> 8) & 31);
                c2 += __shfl_sync(0xFFFFFFFFu, vex, (pw1 >> 16) & 31);
                c3 += __shfl_sync(0xFFFFFFFFu, vex, pw1 >> 24);
            }
            if (words > 2) {
                c0 += __shfl_sync(0xFFFFFFFFu, vex, pw2 & 31);
                c1 += __shfl_sync(0xFFFFFFFFu, vex, (pw2 >> 8) & 31);
                c2 += __shfl_sync(0xFFFFFFFFu, vex, (pw2 >> 16) & 31);
                c3 += __shfl_sync(0xFFFFFFFFu, vex, pw2 >> 24);
            }
            if (words > 3) {
                c0 += __shfl_sync(0xFFFFFFFFu, vex, pw3 & 31);
                c1 += __shfl_sync(0xFFFFFFFFu, vex, (pw3 >> 8) & 31);
                c2 += __shfl_sync(0xFFFFFFFFu, vex, (pw3 >> 16) & 31);
                c3 += __shfl_sync(0xFFFFFFFFu, vex, pw3 >> 24);
            }
            if (words > 4) {
                c0 += __shfl_sync(0xFFFFFFFFu, vex, pw4 & 31);
                c1 += __shfl_sync(0xFFFFFFFFu, vex, (pw4 >> 8) & 31);
                c2 += __shfl_sync(0xFFFFFFFFu, vex, (pw4 >> 16) & 31);
                c3 += __shfl_sync(0xFFFFFFFFu, vex, pw4 >> 24);
            }
            float dn = Pn + ((c0 + c1) + (c2 + c3));
            float e2 = __expf(2.0f * dn);                    // tanh = 1 - 2/(e^{2x}+1)
            float tr = 1.0f - __fdividef(2.0f, e2 + 1.0f);
            vex = tr * wns;

            if (lane == 0) Vp[0] = vex + Vo;
            Vp++;

            float zf  = u2f_small((m >> lane) & 1u);
            float cf  = u2f_small(__popc(m & row));
            float zof = u2f_small((mold >> lane) & 1u);
            float cof = u2f_small(__popc(mold & row));

            FUPD(0, zf, zof) FUPD(1, zf, zof) FUPD(2, zf, zof)
            FUPD(3, cf, cof) FUPD(4, cf, cof) FUPD(5, cf, cof)

            int r = (t + 1) & (CH - 1);
            float syn = shN[r][lane];
            float p0 = fmaf(w0_, F[0], syn);
            float p1 = fmaf(w1_, F[1], w2_ * F[2]);
            float p2 = fmaf(w3_, F[3], w4_ * F[4]);
            float p3 = w5_ * F[5];
            Pn = (p0 + p1) + (p2 + p3);
        }
    }
}

// ---------------- launch ----------------------------------------------------
extern "C" void kernel_launch(void* const* d_in, const int* in_sizes, int n_in,
                              void* d_out, int out_size) {
    const float* Se      = (const float*)d_in[0];
    const float* Si      = (const float*)d_in[1];
    const float* Cden    = (const float*)d_in[2];
    const float* Ce      = (const float*)d_in[3];
    const float* Ci      = (const float*)d_in[4];
    const float* WsSyn   = (const float*)d_in[5];
    const float* WnSyn   = (const float*)d_in[6];
    const float* TauSsyn = (const float*)d_in[7];
    const float* TauNsyn = (const float*)d_in[8];
    const float* DsSyn   = (const float*)d_in[9];
    const float* DnSyn   = (const float*)d_in[10];
    const float* WsH     = (const float*)d_in[11];
    const float* WnH     = (const float*)d_in[12];
    const float* TsH     = (const float*)d_in[13];
    const float* TnH     = (const float*)d_in[14];
    const float* WsP     = (const float*)d_in[15];
    const float* WnP     = (const float*)d_in[16];
    const float* TsP     = (const float*)d_in[17];
    const float* TnP     = (const float*)d_in[18];
    const float* WsSub   = (const float*)d_in[19];
    const float* WnSub   = (const float*)d_in[20];
    const float* ThS     = (const float*)d_in[21];
    const float* ThN     = (const float*)d_in[22];
    const float* Vo      = (const float*)d_in[23];

    int T = in_sizes[0] / ENO;          // 10000
    if (T > TDATA) T = TDATA;
    float* out = (float*)d_out;
    float* V = out;
    float* Z = out + T;

    assign_kernel<<<(ENO + 255) / 256, 256>>>(Ce, Ci);
    reduce_kernel<<<T, 256>>>(Se, Si, T);
    kbuild_kernel<<<(2 * SUBN * 2 * TSYN + 255) / 256, 256>>>(WsSyn, WnSyn, TauSsyn, TauNsyn, DsSyn, DnSyn);
    dim3 cg((T + 255) / 256, SUBN);
    conv_kernel<<<cg, 256>>>(ThS, ThN, T);
    scan_kernel<<<1, 64>>>(Cden, WsH, WnH, TsH, TnH, WsP, WnP, TsP, TnP,
                           WsSub, WnSub, Vo, V, Z, T);
}

// round 4
// speedup vs baseline: 4.9383x; 2.0853x over previous
#include <cuda_runtime.h>
#include <math.h>

#define SUBN  20
#define ENO   2000
#define INO   500
#define TDATA 10000
#define TSYN  200
#define THIST 50
#define CH    64
#define RING  512
#define TPAD  (TDATA + 2 * CH)

// ---------------- scratch (device globals; zero-initialized) ---------------
__device__ int   g_asgE[ENO];
__device__ int   g_asgI[INO];
__device__ float g_inE[SUBN * TDATA];
__device__ float g_inI[SUBN * TDATA];
__device__ float g_kS[SUBN * 2 * TSYN];
__device__ float g_kN[SUBN * 2 * TSYN];
__device__ float g_synST[SUBN * TPAD];          // syn_s - Theta_s, [s][t]
__device__ float g_synNT[SUBN * TPAD];          // syn_ns - Theta_ns

// ---------------- phase 1: one-hot -> assignment indices -------------------
__global__ void assign_kernel(const float* __restrict__ Ce,
                              const float* __restrict__ Ci) {
    int j = blockIdx.x * blockDim.x + threadIdx.x;
    if (j < ENO) {
        int s = 0;
        #pragma unroll
        for (int k = 0; k < SUBN; k++) if (Ce[k * ENO + j] > 0.5f) s = k;
        g_asgE[j] = s;
    }
    if (j < INO) {
        int s = 0;
        #pragma unroll
        for (int k = 0; k < SUBN; k++) if (Ci[k * INO + j] > 0.5f) s = k;
        g_asgI[j] = s;
    }
}

// ---------------- phase 2: sparse scatter-reduce S @ C^T -------------------
__global__ void reduce_kernel(const float* __restrict__ Se,
                              const float* __restrict__ Si, int T) {
    int t = blockIdx.x;
    if (t >= T) return;
    __shared__ float acc[2 * SUBN];
    int tid = threadIdx.x;
    if (tid < 2 * SUBN) acc[tid] = 0.0f;
    __syncthreads();
    for (int j = tid; j < ENO; j += blockDim.x) {
        float v = Se[(size_t)t * ENO + j];
        if (v != 0.0f) atomicAdd(&acc[g_asgE[j]], v);
    }
    for (int j = tid; j < INO; j += blockDim.x) {
        float v = Si[(size_t)t * INO + j];
        if (v != 0.0f) atomicAdd(&acc[SUBN + g_asgI[j]], v);
    }
    __syncthreads();
    if (tid < SUBN)            g_inE[tid * TDATA + t] = acc[tid];
    else if (tid < 2 * SUBN)   g_inI[(tid - SUBN) * TDATA + t] = acc[tid];
}

// ---------------- phase 3: build synaptic kernels ---------------------------
__global__ void kbuild_kernel(const float* __restrict__ Ws,  const float* __restrict__ Wn,
                              const float* __restrict__ TauS, const float* __restrict__ TauN,
                              const float* __restrict__ Ds,  const float* __restrict__ Dn) {
    int idx = blockIdx.x * blockDim.x + threadIdx.x;
    if (idx >= 2 * SUBN * 2 * TSYN) return;
    int k   = idx % TSYN;
    int c   = (idx / TSYN) % 2;
    int s   = (idx / (TSYN * 2)) % SUBN;
    int set = idx / (TSYN * 2 * SUBN);
    const float* W   = set ? Wn   : Ws;
    const float* Tau = set ? TauN : TauS;
    const float* D   = set ? Dn   : Ds;
    double ts = (double)k - exp((double)D[s * 2 + c]);
    if (ts < 0.0) ts = 0.0;
    double acc = 0.0;
    for (int b = 0; b < 3; b++) {
        double Tb = exp((double)Tau[b * 2 + c]);
        double u  = ts / Tb;
        acc += (double)W[s * 6 + b * 2 + c] * u * exp(-u);
    }
    float* out = set ? g_kN : g_kS;
    out[(s * 2 + c) * TSYN + k] = (float)acc;
}

// ---------------- phase 4: causal FIR; folds -Theta into the output --------
__global__ void conv_kernel(const float* __restrict__ ThS,
                            const float* __restrict__ ThN, int T) {
    const int i  = blockIdx.y;
    const int t0 = blockIdx.x * 256;
    __shared__ float she[256 + TSYN - 1];
    __shared__ float shi[256 + TSYN - 1];
    __shared__ float kse[TSYN], ksi[TSYN], kne[TSYN], kni[TSYN];
    int tid = threadIdx.x;
    for (int j = tid; j < 256 + TSYN - 1; j += 256) {
        int tg = t0 - (TSYN - 1) + j;
        bool ok = (tg >= 0 && tg < T);
        she[j] = ok ? g_inE[i * TDATA + tg] : 0.0f;
        shi[j] = ok ? g_inI[i * TDATA + tg] : 0.0f;
    }
    for (int k = tid; k < TSYN; k += 256) {
        kse[k] = g_kS[(i * 2 + 0) * TSYN + k];
        ksi[k] = g_kS[(i * 2 + 1) * TSYN + k];
        kne[k] = g_kN[(i * 2 + 0) * TSYN + k];
        kni[k] = g_kN[(i * 2 + 1) * TSYN + k];
    }
    __syncthreads();
    int t = t0 + tid;
    if (t < T) {
        float as = 0.0f, an = 0.0f;
        #pragma unroll 4
        for (int k = 0; k < TSYN; k++) {
            float xe = she[tid + (TSYN - 1) - k];
            float xi = shi[tid + (TSYN - 1) - k];
            as += xe * kse[k] + xi * ksi[k];
            an += xe * kne[k] + xi * kni[k];
        }
        g_synST[i * TPAD + t] = as - ThS[i];
        g_synNT[i * TPAD + t] = an - ThN[i];
    }
}

// ---------------- phase 5: warp-specialized branchless scan -----------------
__device__ __forceinline__ float u2f_small(unsigned x) {  // exact for x < 2^23
    return __uint_as_float(0x4B000000u | x) - 8388608.0f;
}

#define FUPD(f, x, xo) {                                            \
    float D_ = fmaf(-(xo), fa49[f], E[f]);                          \
    F[f] = fmaf(fa[f], fmaf(-(xo), fg49[f], F[f]), faot[f] * D_);   \
    E[f] = fmaf(fa[f], D_, (x)); }

#define MKCONST(tauH, tauP) {                                       \
    const float* taus_[2] = { tauH, tauP };                         \
    for (int ff = 0; ff < 2; ff++)                                  \
        for (int b = 0; b < 3; b++) {                               \
            double Tb  = exp((double)taus_[ff][b]);                 \
            double a   = exp(-1.0 / Tb);                            \
            double a49 = pow(a, (double)(THIST - 1));               \
            fa[ff*3+b]   = (float)a;                                \
            faot[ff*3+b] = (float)(a / Tb);                         \
            fa49[ff*3+b] = (float)a49;                              \
            fg49[ff*3+b] = (float)((double)(THIST - 1) / Tb * a49); \
        } }

// stage 65 rows: 64 chunk rows + 1 lookahead (each lane its own column only)
#define STAGE65(dst, src, gbase) {                                          \
    const float4* __restrict__ p_ = (const float4*)((src) + lane * TPAD + (gbase)); \
    _Pragma("unroll")                                                       \
    for (int q = 0; q < 16; q++) {                                          \
        float4 a_ = p_[q];                                                  \
        dst[4*q+0][lane] = a_.x; dst[4*q+1][lane] = a_.y;                   \
        dst[4*q+2][lane] = a_.z; dst[4*q+3][lane] = a_.w;                   \
    }                                                                       \
    dst[64][lane] = (src)[lane * TPAD + (gbase) + 64]; }

// ---- producer (z) inner step: fully branchless -----------------------------
#define ZSTEP(jj) {                                                         \
    unsigned mm = m_prev & row;                                             \
    float cs = (lut[0][mm & 31][lane] + lut[1][(mm >> 5) & 31][lane])       \
             + (lut[2][(mm >> 10) & 31][lane] + lut[3][(mm >> 15) & 31][lane]); \
    float ds = cs + Ps;                                                     \
    bool  z  = (ds >= 0.0f);                                                \
    unsigned m = __ballot_sync(0xFFFFFFFFu, z);                             \
    if (lane == 0) rm[t & (RING - 1)] = m;                                  \
    unsigned mold = rm[(t + (RING - 50)) & (RING - 1)];                     \
    float zf = z ? 1.0f : 0.0f;                                             \
    if (act) Zp[lane] = zf;                                                 \
    Zp += SUBN;                                                             \
    float cf  = u2f_small(__popc(m & row));                                 \
    float zof = u2f_small((mold >> lane) & 1u);                             \
    float cof = u2f_small(__popc(mold & row));                              \
    FUPD(0, zf, zof) FUPD(1, zf, zof) FUPD(2, zf, zof)                      \
    FUPD(3, cf, cof) FUPD(4, cf, cof) FUPD(5, cf, cof)                      \
    float syn = shA[(jj) + 1][lane];                                        \
    float p0 = fmaf(w0_, F[0], syn);                                        \
    float p1 = fmaf(w1_, F[1], w2_ * F[2]);                                 \
    float p2 = fmaf(w3_, F[3], w4_ * F[4]);                                 \
    float p3 = w5_ * F[5];                                                  \
    Ps = (p0 + p1) + (p2 + p3);                                             \
    m_prev = m; t++; }

// ---- consumer (ns) inner step; NW = compile-time gather word count --------
#define NSTEP(jj, NW) {                                                     \
    unsigned m_    = rm[t & (RING - 1)];                                    \
    unsigned mold_ = rm[(t + (RING - 50)) & (RING - 1)];                    \
    float c0 = __shfl_sync(0xFFFFFFFFu, vex, pw0 & 31)                      \
             + __shfl_sync(0xFFFFFFFFu, vex, (pw0 >> 8) & 31);              \
    float c1 = __shfl_sync(0xFFFFFFFFu, vex, (pw0 >> 16) & 31)              \
             + __shfl_sync(0xFFFFFFFFu, vex, pw0 >> 24);                    \
    if (NW > 1) {                                                           \
        c0 += __shfl_sync(0xFFFFFFFFu, vex, pw1 & 31)                       \
            + __shfl_sync(0xFFFFFFFFu, vex, (pw1 >> 8) & 31);               \
        c1 += __shfl_sync(0xFFFFFFFFu, vex, (pw1 >> 16) & 31)               \
            + __shfl_sync(0xFFFFFFFFu, vex, pw1 >> 24); }                   \
    if (NW > 2) {                                                           \
        c0 += __shfl_sync(0xFFFFFFFFu, vex, pw2 & 31)                       \
            + __shfl_sync(0xFFFFFFFFu, vex, (pw2 >> 8) & 31);               \
        c1 += __shfl_sync(0xFFFFFFFFu, vex, (pw2 >> 16) & 31)               \
            + __shfl_sync(0xFFFFFFFFu, vex, pw2 >> 24); }                   \
    if (NW > 3) {                                                           \
        c0 += __shfl_sync(0xFFFFFFFFu, vex, pw3 & 31)                       \
            + __shfl_sync(0xFFFFFFFFu, vex, (pw3 >> 8) & 31);               \
        c1 += __shfl_sync(0xFFFFFFFFu, vex, (pw3 >> 16) & 31)               \
            + __shfl_sync(0xFFFFFFFFu, vex, pw3 >> 24); }                   \
    if (NW > 4) {                                                           \
        c0 += __shfl_sync(0xFFFFFFFFu, vex, pw4 & 31)                       \
            + __shfl_sync(0xFFFFFFFFu, vex, (pw4 >> 8) & 31);               \
        c1 += __shfl_sync(0xFFFFFFFFu, vex, (pw4 >> 16) & 31)               \
            + __shfl_sync(0xFFFFFFFFu, vex, pw4 >> 24); }                   \
    float dn = Pn + (c0 + c1);                                              \
    float e2 = __expf(2.0f * dn);                                           \
    float tr = 1.0f - __fdividef(2.0f, e2 + 1.0f);                          \
    vex = tr * wns;                                                         \
    if (lane == 0) Vp[0] = vex + Vo;                                        \
    Vp++;                                                                   \
    float zf  = u2f_small((m_ >> lane) & 1u);                               \
    float cf  = u2f_small(__popc(m_ & row));                                \
    float zof = u2f_small((mold_ >> lane) & 1u);                            \
    float cof = u2f_small(__popc(mold_ & row));                             \
    FUPD(0, zf, zof) FUPD(1, zf, zof) FUPD(2, zf, zof)                      \
    FUPD(3, cf, cof) FUPD(4, cf, cof) FUPD(5, cf, cof)                      \
    float syn = shB[(jj) + 1][lane];                                        \
    float p0 = fmaf(w0_, F[0], syn);                                        \
    float p1 = fmaf(w1_, F[1], w2_ * F[2]);                                 \
    float p2 = fmaf(w3_, F[3], w4_ * F[4]);                                 \
    float p3 = w5_ * F[5];                                                  \
    Pn = (p0 + p1) + (p2 + p3);                                             \
    t++; }

#define NSRUN(NW) {                                                         \
    for (int c = 0; c < nfull; c++) {                                       \
        int t0 = c << 6;                                                    \
        while (s_prod < t0 + CH) {}                                         \
        if (lane == 0) s_cons = t0;                                         \
        _Pragma("unroll 4")                                                 \
        for (int j = 0; j < CH; j++) { NSTEP(j, NW) }                       \
        if (act) STAGE65(shB, g_synNT, t0 + CH);                            \
    }                                                                       \
    while (s_prod < T) {}                                                   \
    if (lane == 0) s_cons = nfull << 6;                                     \
    for (int j = 0; j < rem; j++) { NSTEP(j, NW) } }

__global__ void __launch_bounds__(64, 1)
scan_kernel(const float* __restrict__ Cden,
            const float* __restrict__ WsH, const float* __restrict__ WnH,
            const float* __restrict__ TsH, const float* __restrict__ TnH,
            const float* __restrict__ WsP, const float* __restrict__ WnP,
            const float* __restrict__ TsP, const float* __restrict__ TnP,
            const float* __restrict__ WsSub, const float* __restrict__ WnSub,
            const float* __restrict__ Vop,
            float* __restrict__ V, float* __restrict__ Z, int T)
{
    const int tid  = threadIdx.x;
    const int lane = tid & 31;
    const int wrp  = tid >> 5;
    const bool act = lane < SUBN;

    __shared__ float lut[4][32][32];                 // 16 KB
    __shared__ float shA[CH + 1][32];                // producer syn buffer
    __shared__ float shB[CH + 1][32];                // consumer syn buffer
    __shared__ volatile unsigned rm[RING];           // 2 KB mask ring
    __shared__ volatile int s_prod, s_cons;

    for (int x = tid; x < RING; x += 64) rm[x] = 0u;
    for (int x = tid; x < (CH + 1) * 32; x += 64) {
        ((float*)shA)[x] = 0.0f;
        ((float*)shB)[x] = 0.0f;
    }
    if (tid == 0) { s_prod = 0; s_cons = 0; }

    unsigned row = 0;
    if (act) {
        #pragma unroll
        for (int j = 0; j < SUBN; j++)
            if (Cden[lane * SUBN + j] != 0.0f) row |= (1u << j);
    }

    if (wrp == 0) {
        for (int g = 0; g < 4; g++)
            for (int v = 0; v < 32; v++) {
                float s = 0.0f;
                #pragma unroll
                for (int b = 0; b < 5; b++) {
                    int j = g * 5 + b;
                    if (j < SUBN && ((v >> b) & 1) && ((row >> j) & 1))
                        s += WsSub[j];
                }
                lut[g][v][lane] = s;
            }
    }
    __syncthreads();

    const int nfull = T >> 6;
    const int rem   = T & (CH - 1);

    if (wrp == 0) {
        // ======================= z warp (producer) ==========================
        float fa[6], faot[6], fa49[6], fg49[6];
        MKCONST(TsH, TsP);
        float F[6], E[6];
        #pragma unroll
        for (int f = 0; f < 6; f++) { F[f] = 0.0f; E[f] = 0.0f; }
        float w0_ = 0, w1_ = 0, w2_ = 0, w3_ = 0, w4_ = 0, w5_ = 0;
        if (act) {
            w0_ = WsH[lane * 3 + 0]; w1_ = WsH[lane * 3 + 1]; w2_ = WsH[lane * 3 + 2];
            w3_ = WsP[lane * 3 + 0]; w4_ = WsP[lane * 3 + 1]; w5_ = WsP[lane * 3 + 2];
        }
        if (act) STAGE65(shA, g_synST, 0);

        float Ps = shA[0][lane];
        unsigned m_prev = 0;
        float* Zp = Z;
        int t = 0;

        for (int c = 0; c < nfull; c++) {
            int t0 = c << 6;
            while (s_cons + (RING - 2 * CH) < t0) {}       // ring-space gate
            #pragma unroll 4
            for (int j = 0; j < CH; j++) { ZSTEP(j) }
            __threadfence_block();
            if (lane == 0) s_prod = t0 + CH;
            if (act) STAGE65(shA, g_synST, t0 + CH);       // stage next chunk
        }
        for (int j = 0; j < rem; j++) { ZSTEP(j) }
        __threadfence_block();
        if (lane == 0) s_prod = T;
    } else {
        // ======================= ns warp (consumer) =========================
        float fa[6], faot[6], fa49[6], fg49[6];
        MKCONST(TnH, TnP);
        float F[6], E[6];
        #pragma unroll
        for (int f = 0; f < 6; f++) { F[f] = 0.0f; E[f] = 0.0f; }
        float w0_ = 0, w1_ = 0, w2_ = 0, w3_ = 0, w4_ = 0, w5_ = 0, wns = 0;
        if (act) {
            w0_ = WnH[lane * 3 + 0]; w1_ = WnH[lane * 3 + 1]; w2_ = WnH[lane * 3 + 2];
            w3_ = WnP[lane * 3 + 0]; w4_ = WnP[lane * 3 + 1]; w5_ = WnP[lane * 3 + 2];
            wns = WnSub[lane];
        }
        const float Vo = Vop[0];

        // packed sparse gather indices: 4 per word, 8 bits each, pad = lane 31
        unsigned pw0 = 0x1F1F1F1Fu, pw1 = 0x1F1F1F1Fu, pw2 = 0x1F1F1F1Fu,
                 pw3 = 0x1F1F1F1Fu, pw4 = 0x1F1F1F1Fu;
        {
            unsigned rem_ = row; int k = 0;
            while (rem_) {
                int j = __ffs(rem_) - 1; rem_ &= rem_ - 1;
                unsigned sh = 8u * (k & 3);
                unsigned cl = ~(0xFFu << sh);
                unsigned in = ((unsigned)j) << sh;
                switch (k >> 2) {
                    case 0: pw0 = (pw0 & cl) | in; break;
                    case 1: pw1 = (pw1 & cl) | in; break;
                    case 2: pw2 = (pw2 & cl) | in; break;
                    case 3: pw3 = (pw3 & cl) | in; break;
                    default: pw4 = (pw4 & cl) | in; break;
                }
                k++;
            }
        }
        int kmax = (int)__reduce_max_sync(0xFFFFFFFFu, (unsigned)__popc(row));

        if (act) STAGE65(shB, g_synNT, 0);

        float Pn  = shB[0][lane];
        float vex = 0.0f;
        float* Vp = V;
        int t = 0;

        if (kmax <= 8)       { NSRUN(2) }
        else if (kmax <= 12) { NSRUN(3) }
        else                 { NSRUN(5) }
    }
}

// ---------------- launch ----------------------------------------------------
extern "C" void kernel_launch(void* const* d_in, const int* in_sizes, int n_in,
                              void* d_out, int out_size) {
    const float* Se      = (const float*)d_in[0];
    const float* Si      = (const float*)d_in[1];
    const float* Cden    = (const float*)d_in[2];
    const float* Ce      = (const float*)d_in[3];
    const float* Ci      = (const float*)d_in[4];
    const float* WsSyn   = (const float*)d_in[5];
    const float* WnSyn   = (const float*)d_in[6];
    const float* TauSsyn = (const float*)d_in[7];
    const float* TauNsyn = (const float*)d_in[8];
    const float* DsSyn   = (const float*)d_in[9];
    const float* DnSyn   = (const float*)d_in[10];
    const float* WsH     = (const float*)d_in[11];
    const float* WnH     = (const float*)d_in[12];
    const float* TsH     = (const float*)d_in[13];
    const float* TnH     = (const float*)d_in[14];
    const float* WsP     = (const float*)d_in[15];
    const float* WnP     = (const float*)d_in[16];
    const float* TsP     = (const float*)d_in[17];
    const float* TnP     = (const float*)d_in[18];
    const float* WsSub   = (const float*)d_in[19];
    const float* WnSub   = (const float*)d_in[20];
    const float* ThS     = (const float*)d_in[21];
    const float* ThN     = (const float*)d_in[22];
    const float* Vo      = (const float*)d_in[23];

    int T = in_sizes[0] / ENO;          // 10000
    if (T > TDATA) T = TDATA;
    float* out = (float*)d_out;
    float* V = out;
    float* Z = out + T;

    assign_kernel<<<(ENO + 255) / 256, 256>>>(Ce, Ci);
    reduce_kernel<<<T, 256>>>(Se, Si, T);
    kbuild_kernel<<<(2 * SUBN * 2 * TSYN + 255) / 256, 256>>>(WsSyn, WnSyn, TauSsyn, TauNsyn, DsSyn, DnSyn);
    dim3 cg((T + 255) / 256, SUBN);
    conv_kernel<<<cg, 256>>>(ThS, ThN, T);
    scan_kernel<<<1, 64>>>(Cden, WsH, WnH, TsH, TnH, WsP, WnP, TsP, TnP,
                           WsSub, WnSub, Vo, V, Z, T);
}